// round 14
// baseline (speedup 1.0000x reference)
#include <cuda_runtime.h>
#include <cstdint>

#define N_PROP  2000
#define N_CLS   81
#define N_SORT  2048
#define PAD     300
#define MASK_F  63504      // 28*28*81
#define MASK_F4 15876      // MASK_F / 4
#define N_TILE  63         // ceil(N_PROP/32)
#define HTILE   16         // phase-1 horizon: first 512 boxes (closed system)
#define SROWS   512        // HTILE*32
#define SUPP_W2 16         // words per suppression row in phase-1 block
#define IOU_TH  0.5f

// ---------------- device scratch (no allocations allowed) ----------------
__device__ float4 g_boxes[N_PROP];
__device__ unsigned long long g_keys[N_PROP];
__device__ int    g_sorted[N_SORT];
__device__ float4 g_sboxes[N_PROP];
__device__ unsigned g_supp[SROWS * SUPP_W2];       // 512x512-bit phase-1 suppression block
__device__ int    g_keptpos[PAD];
__device__ int    g_numkept;

// ---------------- K1: per-proposal argmax / max-score / box decode ----------------
__global__ void k1_prep(const float* __restrict__ meta,
                        const float* __restrict__ deltas,
                        const float* __restrict__ props,
                        const float* __restrict__ scores) {
    int warp = (blockIdx.x * blockDim.x + threadIdx.x) >> 5;
    int lane = threadIdx.x & 31;
    if (warp >= N_PROP) return;

    const float* sc = scores + (size_t)warp * N_CLS;
    float bv = -1e30f; int bi = N_CLS; float ms = -1e30f;
    for (int c = lane; c < N_CLS; c += 32) {
        float s = sc[c];
        if (s > bv || (s == bv && c < bi)) { bv = s; bi = c; }
        if (c >= 1) ms = fmaxf(ms, s);
    }
    for (int off = 16; off; off >>= 1) {
        float ov = __shfl_down_sync(0xffffffffu, bv, off);
        int   oi = __shfl_down_sync(0xffffffffu, bi, off);
        float om = __shfl_down_sync(0xffffffffu, ms, off);
        if (ov > bv || (ov == bv && oi < bi)) { bv = ov; bi = oi; }
        ms = fmaxf(ms, om);
    }
    if (lane == 0) {
        float H = meta[0], W = meta[1], scale = meta[2];
        float x1 = props[warp*4+0] / scale, y1 = props[warp*4+1] / scale;
        float x2 = props[warp*4+2] / scale, y2 = props[warp*4+3] / scale;
        float a  = x2 - x1, b = y2 - y1;
        float cx = x1 + 0.5f*a, cy = y1 + 0.5f*b;
        const float* d = deltas + (size_t)warp * (4*N_CLS) + 4*bi;
        float pcx = d[0]*a + cx, pcy = d[1]*b + cy;
        float pw  = expf(d[2])*a, ph = expf(d[3])*b;
        float ox1 = fminf(fmaxf(pcx - 0.5f*pw, 0.f), W - 1.f);
        float oy1 = fminf(fmaxf(pcy - 0.5f*ph, 0.f), H - 1.f);
        float ox2 = fminf(fmaxf(pcx + 0.5f*pw, 0.f), W - 1.f);
        float oy2 = fminf(fmaxf(pcy + 0.5f*ph, 0.f), H - 1.f);
        g_boxes[warp] = make_float4(ox1, oy1, ox2, oy2);

        unsigned u = __float_as_uint(ms);
        u = (u & 0x80000000u) ? ~u : (u | 0x80000000u);
        unsigned hi = ~u;
        g_keys[warp] = ((unsigned long long)hi << 32) | (unsigned)warp;
    }
}

// ---------------- K2: warp-register bitonic sort (smem only for j>=64) ----------------
__device__ __forceinline__ unsigned long long ce64(unsigned long long e, int i, int j, int k) {
    unsigned long long p = __shfl_xor_sync(0xffffffffu, e, j);
    bool keepmin = (((i & j) == 0) == ((i & k) == 0));
    unsigned long long mn = (e < p) ? e : p;
    unsigned long long mx = (e < p) ? p : e;
    return keepmin ? mn : mx;
}

__global__ void __launch_bounds__(1024, 1) k2_sort() {
    __shared__ unsigned long long sk[N_SORT];
    int tid = threadIdx.x, lane = tid & 31, warp = tid >> 5;
    int i0 = warp * 64 + lane, i1 = i0 + 32;
    for (int i = tid; i < N_SORT; i += 1024)
        sk[i] = (i < N_PROP) ? g_keys[i] : 0xFFFFFFFFFFFFFFFFull;
    __syncthreads();
    unsigned long long e0 = sk[i0], e1 = sk[i1];

    #pragma unroll
    for (int kb = 1; kb <= 5; kb++) {
        int k = 1 << kb;
        #pragma unroll
        for (int j = 16; j >= 1; j >>= 1) {
            if (j <= (k >> 1)) { e0 = ce64(e0, i0, j, k); e1 = ce64(e1, i1, j, k); }
        }
    }
    {
        const int k = 64;
        bool up = ((i0 & k) == 0);
        unsigned long long lo = (e0 < e1) ? e0 : e1, hi = (e0 < e1) ? e1 : e0;
        e0 = up ? lo : hi; e1 = up ? hi : lo;
        #pragma unroll
        for (int j = 16; j >= 1; j >>= 1) { e0 = ce64(e0, i0, j, k); e1 = ce64(e1, i1, j, k); }
    }
    #pragma unroll
    for (int kb = 7; kb <= 11; kb++) {
        int k = 1 << kb;
        sk[i0] = e0; sk[i1] = e1;
        __syncthreads();
        for (int j = k >> 1; j >= 64; j >>= 1) {
            int i = ((tid & ~(j - 1)) << 1) | (tid & (j - 1));
            int p = i | j;
            unsigned long long a = sk[i], b = sk[p];
            bool up2 = ((i & k) == 0);
            if (up2 ? (a > b) : (a < b)) { sk[i] = b; sk[p] = a; }
            __syncthreads();
        }
        e0 = sk[i0]; e1 = sk[i1];
        bool up = ((i0 & k) == 0);
        unsigned long long lo = (e0 < e1) ? e0 : e1, hi = (e0 < e1) ? e1 : e0;
        e0 = up ? lo : hi; e1 = up ? hi : lo;
        #pragma unroll
        for (int j = 16; j >= 1; j >>= 1) { e0 = ce64(e0, i0, j, k); e1 = ce64(e1, i1, j, k); }
    }
    int idx0 = (int)(unsigned)(e0 & 0xFFFFFFFFull);
    int idx1 = (int)(unsigned)(e1 & 0xFFFFFFFFull);
    if (i0 < N_PROP) { g_sorted[i0] = idx0; g_sboxes[i0] = g_boxes[idx0]; }
    if (i1 < N_PROP) { g_sorted[i1] = idx1; g_sboxes[i1] = g_boxes[idx1]; }
}

// ---------------- K3: phase-1 suppression block (512 rows x 16 words) ----------------
__global__ void k3_supp() {
    __shared__ float sx1[SROWS], sy1[SROWS], sx2[SROWS], sy2[SROWS], sar[SROWS];
    for (int i = threadIdx.x; i < SROWS; i += blockDim.x) {
        float4 bb = g_sboxes[i];
        sx1[i] = bb.x; sy1[i] = bb.y; sx2[i] = bb.z; sy2[i] = bb.w;
        sar[i] = fmaxf(bb.z - bb.x, 0.f) * fmaxf(bb.w - bb.y, 0.f);
    }
    __syncthreads();
    int lane = threadIdx.x & 31;
    int wid  = threadIdx.x >> 5;
    int base = blockIdx.x * 16;
    for (int task = wid; task < 16 * SUPP_W2; task += 8) {
        int rl = task >> 4;
        int w  = task & 15;
        int ri = base + rl;
        int j  = w * 32 + lane;
        bool bit = false;
        if (j > ri) {
            float ix1 = fmaxf(sx1[ri], sx1[j]);
            float iy1 = fmaxf(sy1[ri], sy1[j]);
            float ix2 = fminf(sx2[ri], sx2[j]);
            float iy2 = fminf(sy2[ri], sy2[j]);
            float inter = fmaxf(ix2 - ix1, 0.f) * fmaxf(iy2 - iy1, 0.f);
            float uni   = fmaxf(sar[ri] + sar[j] - inter, 1e-8f);
            bit = inter > IOU_TH * uni;
        }
        unsigned word = __ballot_sync(0xffffffffu, bit);
        if (lane == 0) g_supp[ri * SUPP_W2 + w] = word;
    }
}

// sign-extended single-bit extract: all-ones if bit `pos` of v is set
__device__ __forceinline__ unsigned bitmask(unsigned v, int pos) {
    int m;
    asm("bfe.s32 %0, %1, %2, 1;" : "=r"(m) : "r"(v), "r"(pos));
    return (unsigned)m;
}

// slow-path helper: suppression word w of row r, computed from smem boxes (ballot)
__device__ __forceinline__ unsigned supp_word(const float* bx1, const float* by1,
        const float* bx2, const float* by2, const float* bar, int r, int w, int lane) {
    int j = w * 32 + lane;
    bool bit = false;
    if (j > r) {
        float ix1 = fmaxf(bx1[r], bx1[j]);
        float iy1 = fmaxf(by1[r], by1[j]);
        float ix2 = fminf(bx2[r], bx2[j]);
        float iy2 = fminf(by2[r], by2[j]);
        float inter = fmaxf(ix2 - ix1, 0.f) * fmaxf(iy2 - iy1, 0.f);
        float uni   = fmaxf(bar[r] + bar[j] - inter, 1e-8f);
        bit = inter > IOU_TH * uni;
    }
    return __ballot_sync(0xffffffffu, bit);
}

// prefetch tile t's diagonal words + rem-update rows into explicit register buffers
__device__ __forceinline__ void k4_fetch(int t, unsigned (&dg)[32], unsigned (&ldr)[16],
                                         int w16, int r0) {
    int p0 = t * 32;
    #pragma unroll
    for (int d = 0; d < 32; d++) dg[d] = g_supp[(p0 + d) * SUPP_W2 + t];
    #pragma unroll
    for (int d = 0; d < 16; d++) ldr[d] = g_supp[(p0 + r0 + d) * SUPP_W2 + w16];
}

// process one 32-box tile: serial closure + horizon rem update. Returns kc>=PAD.
__device__ __forceinline__ bool k4_proc(int t, const unsigned (&dg)[32], const unsigned (&ldr)[16],
        unsigned &remlo, int &kc, unsigned* smrem, int lane, int r0) {
    const unsigned F = 0xffffffffu;
    unsigned curw = __shfl_sync(F, remlo, t);        // seed (1 shfl/tile)
    #pragma unroll
    for (int d = 0; d < 32; d++)                     // serial closure: BFE+LOP3 per box
        curw |= dg[d] & ~bitmask(curw, d);
    unsigned kw = ~curw;
    if (lane == 0) smrem[t] = curw;
    kc += __popc(kw);
    unsigned u0 = 0, u1 = 0, u2 = 0, u3 = 0;         // tree-reduced horizon rem update
    #pragma unroll
    for (int d = 0; d < 4; d++) {
        u0 |= ldr[d]      & bitmask(kw, r0 + d);
        u1 |= ldr[d + 4]  & bitmask(kw, r0 + d + 4);
        u2 |= ldr[d + 8]  & bitmask(kw, r0 + d + 8);
        u3 |= ldr[d + 12] & bitmask(kw, r0 + d + 12);
    }
    unsigned upd = (u0 | u1) | (u2 | u3);
    upd |= __shfl_xor_sync(F, upd, 16);
    remlo |= upd;
    return kc >= PAD;
}

// ---------------- K4: greedy NMS — compact code (I$-resident), register ping-pong ----------------
// Rolled tile loop unrolled x2 with EXPLICIT ping-pong buffers (dA/lA <-> dB/lB): all array
// indices compile-time constant -> register-resident (no spill, launch_bounds(32,1) gives
// full RF); body ~6.5KB -> fits instruction cache (the R10-R13 full unroll was ~38KB and
// I$-bound at 16us). Prefetch runs one tile ahead of consumption.
__global__ void __launch_bounds__(32, 1) k4_nms() {
    __shared__ unsigned smrem[N_TILE + 1];
    __shared__ float bx1[N_SORT], by1[N_SORT], bx2[N_SORT], by2[N_SORT], bar[N_SORT];
    const unsigned F = 0xffffffffu;
    int lane = threadIdx.x;
    unsigned remlo = 0;                   // lane l<16 owns horizon rem word l (dup in l+16..)
    int kc = 0, ntiles = N_TILE;
    bool done = false;
    int w16 = lane & 15, r0 = lane & 16;

    unsigned dA[32], lA[16], dB[32], lB[16];
    k4_fetch(0, dA, lA, w16, r0);

    for (int t = 0; t < HTILE; t += 2) {
        if (t + 1 < HTILE) k4_fetch(t + 1, dB, lB, w16, r0);   // prefetch (off-chain)
        if (k4_proc(t, dA, lA, remlo, kc, smrem, lane, r0)) { ntiles = t + 1; done = true; break; }
        if (t + 2 < HTILE) k4_fetch(t + 2, dA, lA, w16, r0);   // prefetch (off-chain)
        if (k4_proc(t + 1, dB, lB, remlo, kc, smrem, lane, r0)) { ntiles = t + 2; done = true; break; }
    }

    if (!done) {
        // RARE: horizon exceeded. Compute suppression on the fly from sorted boxes.
        for (int i = lane; i < N_SORT; i += 32) {
            float4 bb = (i < N_PROP) ? g_sboxes[i] : make_float4(0.f, 0.f, 0.f, 0.f);
            bx1[i] = bb.x; by1[i] = bb.y; bx2[i] = bb.z; by2[i] = bb.w;
            bar[i] = fmaxf(bb.z - bb.x, 0.f) * fmaxf(bb.w - bb.y, 0.f);
        }
        __syncwarp();
        unsigned rem0 = 0, rem1 = 0;
        for (int tt = 0; tt < HTILE; tt++) {
            unsigned kw = ~smrem[tt];
            while (kw) {
                int d = __ffs(kw) - 1; kw &= kw - 1;
                int r = tt * 32 + d;
                for (int w = 0; w < 64; w++) {
                    unsigned word = supp_word(bx1, by1, bx2, by2, bar, r, w, lane);
                    if (w < 32) { if (lane == w)      rem0 |= word; }
                    else        { if (lane == w - 32) rem1 |= word; }
                }
            }
        }
        for (int t = HTILE; t < N_TILE; t++) {
            int p0 = t * 32;
            unsigned curw = __shfl_sync(F, (t < 32) ? rem0 : rem1, t & 31);
            for (int d = 0; d < 32; d++) {
                unsigned s = supp_word(bx1, by1, bx2, by2, bar, p0 + d, t, lane);
                curw |= s & ~bitmask(curw, d);
            }
            unsigned valid = (t < 62) ? 0xffffffffu : 0xffffu;
            unsigned kw = (~curw) & valid;
            if (lane == 0) smrem[t] = curw;
            kc += __popc(kw);
            unsigned kwi = kw;
            while (kwi) {
                int d = __ffs(kwi) - 1; kwi &= kwi - 1;
                int r = p0 + d;
                for (int w = t; w < 64; w++) {
                    unsigned word = supp_word(bx1, by1, bx2, by2, bar, r, w, lane);
                    if (w < 32) { if (lane == w)      rem0 |= word; }
                    else        { if (lane == w - 32) rem1 |= word; }
                }
            }
            if (kc >= PAD) { ntiles = t + 1; break; }
        }
    }
    __syncwarp();

    // Reconstruct kept positions: popc + warp exclusive scan + bit enumerate
    int total = 0;
    #pragma unroll
    for (int rnd = 0; rnd < 2; rnd++) {
        int idx = rnd * 32 + lane;
        unsigned valid = (idx < 62) ? 0xffffffffu : ((idx == 62) ? 0xffffu : 0u);
        unsigned kw = (idx < ntiles) ? ((~smrem[idx]) & valid) : 0u;
        int c = __popc(kw);
        int inc = c;
        #pragma unroll
        for (int o = 1; o < 32; o <<= 1) {
            int v = __shfl_up_sync(0xffffffffu, inc, o);
            if (lane >= o) inc += v;
        }
        int slot = total + inc - c;
        while (kw) {
            int b = __ffs(kw) - 1; kw &= kw - 1;
            if (slot < PAD) g_keptpos[slot] = idx * 32 + b;
            slot++;
        }
        total += __shfl_sync(0xffffffffu, inc, 31);
    }
    if (lane == 31) g_numkept = (total < PAD) ? total : PAD;
}

// ---------------- K5: gather/scatter outputs (DRAM-bound, float4) ----------------
__global__ void k5_out(const float* __restrict__ scores,
                       const float* __restrict__ masks,
                       float* __restrict__ out) {
    int r  = blockIdx.y;
    int nk = g_numkept;
    int src = -1;
    if (r < nk) src = g_sorted[g_keptpos[r]];

    int c = blockIdx.x * blockDim.x + threadIdx.x;
    if (c < MASK_F4) {
        float4 v = make_float4(0.f, 0.f, 0.f, 0.f);
        if (src >= 0)
            v = reinterpret_cast<const float4*>(masks)[(size_t)src * MASK_F4 + c];
        reinterpret_cast<float4*>(out + PAD*4 + PAD*N_CLS)[(size_t)r * MASK_F4 + c] = v;
    }
    if (blockIdx.x == 0) {
        int t = threadIdx.x;
        if (t < 4) {
            float v = 0.f;
            if (src >= 0) v = reinterpret_cast<const float*>(g_boxes)[src*4 + t];
            out[r*4 + t] = v;
        } else if (t < 4 + N_CLS) {
            int cc = t - 4;
            float v = 0.f;
            if (src >= 0) v = scores[(size_t)src * N_CLS + cc];
            out[PAD*4 + r*N_CLS + cc] = v;
        }
    }
}

// ---------------- launch ----------------
extern "C" void kernel_launch(void* const* d_in, const int* in_sizes, int n_in,
                              void* d_out, int out_size) {
    const float* meta    = (const float*)d_in[0];
    const float* deltas  = (const float*)d_in[1];
    const float* props   = (const float*)d_in[2];
    const float* scores  = (const float*)d_in[3];
    const float* masks   = (const float*)d_in[4];
    float* out = (float*)d_out;

    k1_prep<<<(N_PROP * 32 + 255) / 256, 256>>>(meta, deltas, props, scores);
    k2_sort<<<1, 1024>>>();
    k3_supp<<<SROWS / 16, 256>>>();
    k4_nms<<<1, 32>>>();
    dim3 g5((MASK_F4 + 255) / 256, PAD);
    k5_out<<<g5, 256>>>(scores, masks, out);
}

// round 15
// speedup vs baseline: 1.0102x; 1.0102x over previous
#include <cuda_runtime.h>
#include <cstdint>

#define N_PROP  2000
#define N_CLS   81
#define N_SORT  2048
#define PAD     300
#define MASK_F  63504      // 28*28*81
#define MASK_F4 15876      // MASK_F / 4
#define N_TILE  63         // ceil(N_PROP/32)
#define HTILE   16         // phase-1 horizon: first 512 boxes (closed system)
#define SROWS   512        // HTILE*32
#define SUPP_W2 16         // words per suppression row in phase-1 block
#define IOU_TH  0.5f

// ---------------- device scratch (no allocations allowed) ----------------
__device__ float4 g_boxes[N_PROP];
__device__ unsigned long long g_keys[N_PROP];
__device__ int    g_sorted[N_SORT];
__device__ float4 g_sboxes[N_PROP];
__device__ unsigned g_supp[SROWS * SUPP_W2];       // 512x512-bit phase-1 suppression block
__device__ int    g_keptpos[PAD];
__device__ int    g_numkept;

// ---------------- K1: per-proposal argmax / max-score / box decode ----------------
__global__ void k1_prep(const float* __restrict__ meta,
                        const float* __restrict__ deltas,
                        const float* __restrict__ props,
                        const float* __restrict__ scores) {
    int warp = (blockIdx.x * blockDim.x + threadIdx.x) >> 5;
    int lane = threadIdx.x & 31;
    if (warp >= N_PROP) return;

    const float* sc = scores + (size_t)warp * N_CLS;
    float bv = -1e30f; int bi = N_CLS; float ms = -1e30f;
    for (int c = lane; c < N_CLS; c += 32) {
        float s = sc[c];
        if (s > bv || (s == bv && c < bi)) { bv = s; bi = c; }
        if (c >= 1) ms = fmaxf(ms, s);
    }
    for (int off = 16; off; off >>= 1) {
        float ov = __shfl_down_sync(0xffffffffu, bv, off);
        int   oi = __shfl_down_sync(0xffffffffu, bi, off);
        float om = __shfl_down_sync(0xffffffffu, ms, off);
        if (ov > bv || (ov == bv && oi < bi)) { bv = ov; bi = oi; }
        ms = fmaxf(ms, om);
    }
    if (lane == 0) {
        float H = meta[0], W = meta[1], scale = meta[2];
        float x1 = props[warp*4+0] / scale, y1 = props[warp*4+1] / scale;
        float x2 = props[warp*4+2] / scale, y2 = props[warp*4+3] / scale;
        float a  = x2 - x1, b = y2 - y1;
        float cx = x1 + 0.5f*a, cy = y1 + 0.5f*b;
        const float* d = deltas + (size_t)warp * (4*N_CLS) + 4*bi;
        float pcx = d[0]*a + cx, pcy = d[1]*b + cy;
        float pw  = expf(d[2])*a, ph = expf(d[3])*b;
        float ox1 = fminf(fmaxf(pcx - 0.5f*pw, 0.f), W - 1.f);
        float oy1 = fminf(fmaxf(pcy - 0.5f*ph, 0.f), H - 1.f);
        float ox2 = fminf(fmaxf(pcx + 0.5f*pw, 0.f), W - 1.f);
        float oy2 = fminf(fmaxf(pcy + 0.5f*ph, 0.f), H - 1.f);
        g_boxes[warp] = make_float4(ox1, oy1, ox2, oy2);

        unsigned u = __float_as_uint(ms);
        u = (u & 0x80000000u) ? ~u : (u | 0x80000000u);
        unsigned hi = ~u;
        g_keys[warp] = ((unsigned long long)hi << 32) | (unsigned)warp;
    }
}

// ---------------- K2: warp-register bitonic sort (smem only for j>=64) ----------------
__device__ __forceinline__ unsigned long long ce64(unsigned long long e, int i, int j, int k) {
    unsigned long long p = __shfl_xor_sync(0xffffffffu, e, j);
    bool keepmin = (((i & j) == 0) == ((i & k) == 0));
    unsigned long long mn = (e < p) ? e : p;
    unsigned long long mx = (e < p) ? p : e;
    return keepmin ? mn : mx;
}

__global__ void __launch_bounds__(1024, 1) k2_sort() {
    __shared__ unsigned long long sk[N_SORT];
    int tid = threadIdx.x, lane = tid & 31, warp = tid >> 5;
    int i0 = warp * 64 + lane, i1 = i0 + 32;
    for (int i = tid; i < N_SORT; i += 1024)
        sk[i] = (i < N_PROP) ? g_keys[i] : 0xFFFFFFFFFFFFFFFFull;
    __syncthreads();
    unsigned long long e0 = sk[i0], e1 = sk[i1];

    #pragma unroll
    for (int kb = 1; kb <= 5; kb++) {
        int k = 1 << kb;
        #pragma unroll
        for (int j = 16; j >= 1; j >>= 1) {
            if (j <= (k >> 1)) { e0 = ce64(e0, i0, j, k); e1 = ce64(e1, i1, j, k); }
        }
    }
    {
        const int k = 64;
        bool up = ((i0 & k) == 0);
        unsigned long long lo = (e0 < e1) ? e0 : e1, hi = (e0 < e1) ? e1 : e0;
        e0 = up ? lo : hi; e1 = up ? hi : lo;
        #pragma unroll
        for (int j = 16; j >= 1; j >>= 1) { e0 = ce64(e0, i0, j, k); e1 = ce64(e1, i1, j, k); }
    }
    #pragma unroll
    for (int kb = 7; kb <= 11; kb++) {
        int k = 1 << kb;
        sk[i0] = e0; sk[i1] = e1;
        __syncthreads();
        for (int j = k >> 1; j >= 64; j >>= 1) {
            int i = ((tid & ~(j - 1)) << 1) | (tid & (j - 1));
            int p = i | j;
            unsigned long long a = sk[i], b = sk[p];
            bool up2 = ((i & k) == 0);
            if (up2 ? (a > b) : (a < b)) { sk[i] = b; sk[p] = a; }
            __syncthreads();
        }
        e0 = sk[i0]; e1 = sk[i1];
        bool up = ((i0 & k) == 0);
        unsigned long long lo = (e0 < e1) ? e0 : e1, hi = (e0 < e1) ? e1 : e0;
        e0 = up ? lo : hi; e1 = up ? hi : lo;
        #pragma unroll
        for (int j = 16; j >= 1; j >>= 1) { e0 = ce64(e0, i0, j, k); e1 = ce64(e1, i1, j, k); }
    }
    int idx0 = (int)(unsigned)(e0 & 0xFFFFFFFFull);
    int idx1 = (int)(unsigned)(e1 & 0xFFFFFFFFull);
    if (i0 < N_PROP) { g_sorted[i0] = idx0; g_sboxes[i0] = g_boxes[idx0]; }
    if (i1 < N_PROP) { g_sorted[i1] = idx1; g_sboxes[i1] = g_boxes[idx1]; }
}

// ---------------- K3: phase-1 suppression block (512 rows x 16 words) ----------------
__global__ void k3_supp() {
    __shared__ float sx1[SROWS], sy1[SROWS], sx2[SROWS], sy2[SROWS], sar[SROWS];
    for (int i = threadIdx.x; i < SROWS; i += blockDim.x) {
        float4 bb = g_sboxes[i];
        sx1[i] = bb.x; sy1[i] = bb.y; sx2[i] = bb.z; sy2[i] = bb.w;
        sar[i] = fmaxf(bb.z - bb.x, 0.f) * fmaxf(bb.w - bb.y, 0.f);
    }
    __syncthreads();
    int lane = threadIdx.x & 31;
    int wid  = threadIdx.x >> 5;
    int base = blockIdx.x * 16;
    for (int task = wid; task < 16 * SUPP_W2; task += 8) {
        int rl = task >> 4;
        int w  = task & 15;
        int ri = base + rl;
        int j  = w * 32 + lane;
        bool bit = false;
        if (j > ri) {
            float ix1 = fmaxf(sx1[ri], sx1[j]);
            float iy1 = fmaxf(sy1[ri], sy1[j]);
            float ix2 = fminf(sx2[ri], sx2[j]);
            float iy2 = fminf(sy2[ri], sy2[j]);
            float inter = fmaxf(ix2 - ix1, 0.f) * fmaxf(iy2 - iy1, 0.f);
            float uni   = fmaxf(sar[ri] + sar[j] - inter, 1e-8f);
            bit = inter > IOU_TH * uni;
        }
        unsigned word = __ballot_sync(0xffffffffu, bit);
        if (lane == 0) g_supp[ri * SUPP_W2 + w] = word;
    }
}

// sign-extended single-bit extract: all-ones if bit `pos` of v is set
__device__ __forceinline__ unsigned bitmask(unsigned v, int pos) {
    int m;
    asm("bfe.s32 %0, %1, %2, 1;" : "=r"(m) : "r"(v), "r"(pos));
    return (unsigned)m;
}

// slow-path helper: suppression word w of row r, computed from smem boxes (ballot)
__device__ __forceinline__ unsigned supp_word(const float* bx1, const float* by1,
        const float* bx2, const float* by2, const float* bar, int r, int w, int lane) {
    int j = w * 32 + lane;
    bool bit = false;
    if (j > r) {
        float ix1 = fmaxf(bx1[r], bx1[j]);
        float iy1 = fmaxf(by1[r], by1[j]);
        float ix2 = fminf(bx2[r], bx2[j]);
        float iy2 = fminf(by2[r], by2[j]);
        float inter = fmaxf(ix2 - ix1, 0.f) * fmaxf(iy2 - iy1, 0.f);
        float uni   = fmaxf(bar[r] + bar[j] - inter, 1e-8f);
        bit = inter > IOU_TH * uni;
    }
    return __ballot_sync(0xffffffffu, bit);
}

// prefetch tile t's diagonal words + rem-update rows into explicit register buffers
__device__ __forceinline__ void k4_fetch(int t, unsigned (&dg)[32], unsigned (&ldr)[16],
                                         int w16, int r0) {
    int p0 = t * 32;
    #pragma unroll
    for (int d = 0; d < 32; d++) dg[d] = g_supp[(p0 + d) * SUPP_W2 + t];
    #pragma unroll
    for (int d = 0; d < 16; d++) ldr[d] = g_supp[(p0 + r0 + d) * SUPP_W2 + w16];
}

// process one 32-box tile: serial closure + horizon rem update. Returns kc>=PAD.
__device__ __forceinline__ bool k4_proc(int t, const unsigned (&dg)[32], const unsigned (&ldr)[16],
        unsigned &remlo, int &kc, unsigned* smrem, int lane, int r0) {
    const unsigned F = 0xffffffffu;
    unsigned curw = __shfl_sync(F, remlo, t);        // seed (1 shfl/tile)
    #pragma unroll
    for (int d = 0; d < 32; d++)                     // serial closure: BFE+LOP3 per box
        curw |= dg[d] & ~bitmask(curw, d);
    unsigned kw = ~curw;
    if (lane == 0) smrem[t] = curw;
    kc += __popc(kw);
    unsigned u0 = 0, u1 = 0, u2 = 0, u3 = 0;         // tree-reduced horizon rem update
    #pragma unroll
    for (int d = 0; d < 4; d++) {
        u0 |= ldr[d]      & bitmask(kw, r0 + d);
        u1 |= ldr[d + 4]  & bitmask(kw, r0 + d + 4);
        u2 |= ldr[d + 8]  & bitmask(kw, r0 + d + 8);
        u3 |= ldr[d + 12] & bitmask(kw, r0 + d + 12);
    }
    unsigned upd = (u0 | u1) | (u2 | u3);
    upd |= __shfl_xor_sync(F, upd, 16);
    remlo |= upd;
    return kc >= PAD;
}

// ---------------- K4: greedy NMS — compact code, register triple-buffer (distance-2 prefetch) ----------------
// L2 is fully evicted between graph replays by k5's 152MB stream, so g_supp reads can be
// DRAM-latency; distance-2 prefetch (~600+cyc issue->consume) covers it. All buffer indices
// compile-time constant -> register-resident (launch_bounds(32,1) = full RF).
__global__ void __launch_bounds__(32, 1) k4_nms() {
    __shared__ unsigned smrem[N_TILE + 1];
    __shared__ float bx1[N_SORT], by1[N_SORT], bx2[N_SORT], by2[N_SORT], bar[N_SORT];
    const unsigned F = 0xffffffffu;
    int lane = threadIdx.x;
    unsigned remlo = 0;                   // lane l<16 owns horizon rem word l (dup in l+16..)
    int kc = 0, ntiles = N_TILE;
    bool done = false;
    int w16 = lane & 15, r0 = lane & 16;

    unsigned dA[32], lA[16], dB[32], lB[16], dC[32], lC[16];
    k4_fetch(0, dA, lA, w16, r0);
    k4_fetch(1, dB, lB, w16, r0);

    for (int t = 0; t < HTILE; t += 3) {              // tile k uses buffer (k mod 3)
        if (t + 2 < HTILE) k4_fetch(t + 2, dC, lC, w16, r0);
        if (k4_proc(t, dA, lA, remlo, kc, smrem, lane, r0)) { ntiles = t + 1; done = true; break; }
        if (t + 1 >= HTILE) break;
        if (t + 3 < HTILE) k4_fetch(t + 3, dA, lA, w16, r0);
        if (k4_proc(t + 1, dB, lB, remlo, kc, smrem, lane, r0)) { ntiles = t + 2; done = true; break; }
        if (t + 2 >= HTILE) break;
        if (t + 4 < HTILE) k4_fetch(t + 4, dB, lB, w16, r0);
        if (k4_proc(t + 2, dC, lC, remlo, kc, smrem, lane, r0)) { ntiles = t + 3; done = true; break; }
    }

    if (!done && kc < PAD) {
        // RARE: horizon exceeded. Compute suppression on the fly from sorted boxes.
        for (int i = lane; i < N_SORT; i += 32) {
            float4 bb = (i < N_PROP) ? g_sboxes[i] : make_float4(0.f, 0.f, 0.f, 0.f);
            bx1[i] = bb.x; by1[i] = bb.y; bx2[i] = bb.z; by2[i] = bb.w;
            bar[i] = fmaxf(bb.z - bb.x, 0.f) * fmaxf(bb.w - bb.y, 0.f);
        }
        __syncwarp();
        unsigned rem0 = 0, rem1 = 0;
        for (int tt = 0; tt < HTILE; tt++) {
            unsigned kw = ~smrem[tt];
            while (kw) {
                int d = __ffs(kw) - 1; kw &= kw - 1;
                int r = tt * 32 + d;
                for (int w = 0; w < 64; w++) {
                    unsigned word = supp_word(bx1, by1, bx2, by2, bar, r, w, lane);
                    if (w < 32) { if (lane == w)      rem0 |= word; }
                    else        { if (lane == w - 32) rem1 |= word; }
                }
            }
        }
        for (int t = HTILE; t < N_TILE; t++) {
            int p0 = t * 32;
            unsigned curw = __shfl_sync(F, (t < 32) ? rem0 : rem1, t & 31);
            for (int d = 0; d < 32; d++) {
                unsigned s = supp_word(bx1, by1, bx2, by2, bar, p0 + d, t, lane);
                curw |= s & ~bitmask(curw, d);
            }
            unsigned valid = (t < 62) ? 0xffffffffu : 0xffffu;
            unsigned kw = (~curw) & valid;
            if (lane == 0) smrem[t] = curw;
            kc += __popc(kw);
            unsigned kwi = kw;
            while (kwi) {
                int d = __ffs(kwi) - 1; kwi &= kwi - 1;
                int r = p0 + d;
                for (int w = t; w < 64; w++) {
                    unsigned word = supp_word(bx1, by1, bx2, by2, bar, r, w, lane);
                    if (w < 32) { if (lane == w)      rem0 |= word; }
                    else        { if (lane == w - 32) rem1 |= word; }
                }
            }
            if (kc >= PAD) { ntiles = t + 1; break; }
        }
    }
    __syncwarp();

    // Reconstruct kept positions: popc + warp exclusive scan + bit enumerate
    int total = 0;
    #pragma unroll
    for (int rnd = 0; rnd < 2; rnd++) {
        int idx = rnd * 32 + lane;
        unsigned valid = (idx < 62) ? 0xffffffffu : ((idx == 62) ? 0xffffu : 0u);
        unsigned kw = (idx < ntiles) ? ((~smrem[idx]) & valid) : 0u;
        int c = __popc(kw);
        int inc = c;
        #pragma unroll
        for (int o = 1; o < 32; o <<= 1) {
            int v = __shfl_up_sync(0xffffffffu, inc, o);
            if (lane >= o) inc += v;
        }
        int slot = total + inc - c;
        while (kw) {
            int b = __ffs(kw) - 1; kw &= kw - 1;
            if (slot < PAD) g_keptpos[slot] = idx * 32 + b;
            slot++;
        }
        total += __shfl_sync(0xffffffffu, inc, 31);
    }
    if (lane == 31) g_numkept = (total < PAD) ? total : PAD;
}

// ---------------- K5: one block per output row — amortized indirection, deep MLP ----------------
__global__ void __launch_bounds__(256, 8) k5_out(const float* __restrict__ scores,
                                                 const float* __restrict__ masks,
                                                 float* __restrict__ out) {
    __shared__ int s_src;
    int r = blockIdx.x;
    if (threadIdx.x == 0) {
        int nk = g_numkept;
        s_src = (r < nk) ? g_sorted[g_keptpos[r]] : -1;
    }
    __syncthreads();
    int src = s_src;

    // mask row: 15876 float4s, 256 threads -> 62.02 iters
    const float4* min4 = (src >= 0) ? (reinterpret_cast<const float4*>(masks) + (size_t)src * MASK_F4)
                                    : nullptr;
    float4* mout = reinterpret_cast<float4*>(out + PAD*4 + PAD*N_CLS) + (size_t)r * MASK_F4;
    if (src >= 0) {
        #pragma unroll 4
        for (int i = threadIdx.x; i < MASK_F4; i += 256)
            mout[i] = min4[i];
    } else {
        float4 z = make_float4(0.f, 0.f, 0.f, 0.f);
        #pragma unroll 4
        for (int i = threadIdx.x; i < MASK_F4; i += 256)
            mout[i] = z;
    }

    // boxes (4 floats) + scores (81 floats) for this row
    int t = threadIdx.x;
    if (t < 4) {
        float v = 0.f;
        if (src >= 0) v = reinterpret_cast<const float*>(g_boxes)[src*4 + t];
        out[r*4 + t] = v;
    } else if (t < 4 + N_CLS) {
        int cc = t - 4;
        float v = 0.f;
        if (src >= 0) v = scores[(size_t)src * N_CLS + cc];
        out[PAD*4 + r*N_CLS + cc] = v;
    }
}

// ---------------- launch ----------------
extern "C" void kernel_launch(void* const* d_in, const int* in_sizes, int n_in,
                              void* d_out, int out_size) {
    const float* meta    = (const float*)d_in[0];
    const float* deltas  = (const float*)d_in[1];
    const float* props   = (const float*)d_in[2];
    const float* scores  = (const float*)d_in[3];
    const float* masks   = (const float*)d_in[4];
    float* out = (float*)d_out;

    k1_prep<<<(N_PROP * 32 + 255) / 256, 256>>>(meta, deltas, props, scores);
    k2_sort<<<1, 1024>>>();
    k3_supp<<<SROWS / 16, 256>>>();
    k4_nms<<<1, 32>>>();
    k5_out<<<PAD, 256>>>(scores, masks, out);
}